// round 11
// baseline (speedup 1.0000x reference)
#include <cuda_runtime.h>
#include <cstdint>

// ModelVoxel: out[p] = f[i,j,k] with i,j,k = (int)clip((x[p]+1)/h, 0, 255),
// h = 2/255, f is 256^3 fp32 (64 MB, mostly L2-resident via evict_last hint).
//
// R10: 8 points/thread WITH occupancy preserved.
//  - __launch_bounds__(256, 8) caps regs at 32 -> 64 warps/SM (R9 lost to
//    occupancy: 38 regs -> 64.6% occ).
//  - 2-stage pipeline: {load abc, idx, gather o0} then {load deg (overlaps
//    o0 gathers), idx, gather o1}, 2x STG.128. Peak live set fits 32 regs.
//  - Cache policy (R7 win): x __ldcs, out __stcs, f evict_last policy reg.

static __device__ __forceinline__ int vox1(float v) {
    const float h = 2.0f / 255.0f;           // replicate reference's fp32 h
    float p = (v + 1.0f) / h;                // same op order as reference
    p = fminf(fmaxf(p, 0.0f), 255.0f);       // clip
    return (int)p;                           // truncation == astype(int32) (p >= 0)
}

static __device__ __forceinline__ uint64_t make_evict_last_policy() {
    uint64_t pol;
    asm("createpolicy.fractional.L2::evict_last.b64 %0, 1.0;" : "=l"(pol));
    return pol;
}

static __device__ __forceinline__ float ldg_pin_l2(const float* p, uint64_t pol) {
    float v;
    asm("ld.global.nc.L2::cache_hint.f32 %0, [%1], %2;"
        : "=f"(v) : "l"(p), "l"(pol));
    return v;
}

__global__ void __launch_bounds__(256, 8) voxel_gather8p_kernel(
    const float4* __restrict__ x4,   // 6 float4s per 8 points
    const float*  __restrict__ f,    // 256^3 grid
    float4*       __restrict__ out4, // 2 float4s per 8 points
    int n8)                          // number of 8-point groups
{
    int t = blockIdx.x * blockDim.x + threadIdx.x;
    if (t >= n8) return;

    const uint64_t pol = make_evict_last_policy();
    const float4* p = x4 + 6 * (size_t)t;

    // ── Stage 1: points 0-3 ──────────────────────────────────────────
    float4 a = __ldcs(p + 0);
    float4 b = __ldcs(p + 1);
    float4 c = __ldcs(p + 2);

    int i0 = (vox1(a.x) << 16) | (vox1(a.y) << 8) | vox1(a.z);
    int i1 = (vox1(a.w) << 16) | (vox1(b.x) << 8) | vox1(b.y);
    int i2 = (vox1(b.z) << 16) | (vox1(b.w) << 8) | vox1(c.x);
    int i3 = (vox1(c.y) << 16) | (vox1(c.z) << 8) | vox1(c.w);

    float4 o0;
    o0.x = ldg_pin_l2(f + i0, pol);
    o0.y = ldg_pin_l2(f + i1, pol);
    o0.z = ldg_pin_l2(f + i2, pol);
    o0.w = ldg_pin_l2(f + i3, pol);

    // ── Stage 2: points 4-7 (x loads overlap the o0 gathers) ─────────
    float4 d = __ldcs(p + 3);
    float4 e = __ldcs(p + 4);
    float4 g = __ldcs(p + 5);

    int i4 = (vox1(d.x) << 16) | (vox1(d.y) << 8) | vox1(d.z);
    int i5 = (vox1(d.w) << 16) | (vox1(e.x) << 8) | vox1(e.y);
    int i6 = (vox1(e.z) << 16) | (vox1(e.w) << 8) | vox1(g.x);
    int i7 = (vox1(g.y) << 16) | (vox1(g.z) << 8) | vox1(g.w);

    float4 o1;
    o1.x = ldg_pin_l2(f + i4, pol);
    o1.y = ldg_pin_l2(f + i5, pol);
    o1.z = ldg_pin_l2(f + i6, pol);
    o1.w = ldg_pin_l2(f + i7, pol);

    __stcs(out4 + 2 * (size_t)t + 0, o0);
    __stcs(out4 + 2 * (size_t)t + 1, o1);
}

// Tail handler for n not divisible by 8 (not needed for 16777216, but cheap).
__global__ void voxel_gather_tail_kernel(
    const float* __restrict__ x,
    const float* __restrict__ f,
    float*       __restrict__ out,
    int start, int n)
{
    int i = start + blockIdx.x * blockDim.x + threadIdx.x;
    if (i >= n) return;
    const uint64_t pol = make_evict_last_policy();
    int ix = vox1(x[3 * (size_t)i + 0]);
    int iy = vox1(x[3 * (size_t)i + 1]);
    int iz = vox1(x[3 * (size_t)i + 2]);
    out[i] = ldg_pin_l2(f + ((ix << 16) | (iy << 8) | iz), pol);
}

extern "C" void kernel_launch(void* const* d_in, const int* in_sizes, int n_in,
                              void* d_out, int out_size) {
    const float* x = (const float*)d_in[0];   // (N, 3) fp32
    const float* f = (const float*)d_in[1];   // (256,256,256) fp32
    float* out = (float*)d_out;               // (N,) fp32

    int n  = in_sizes[0] / 3;                 // number of points
    int n8 = n / 8;

    if (n8 > 0) {
        int threads = 256;
        int blocks = (n8 + threads - 1) / threads;
        voxel_gather8p_kernel<<<blocks, threads>>>(
            (const float4*)x, f, (float4*)out, n8);
    }
    int rem_start = n8 * 8;
    if (rem_start < n) {
        int rem = n - rem_start;
        voxel_gather_tail_kernel<<<(rem + 255) / 256, 256>>>(
            x, f, out, rem_start, n);
    }
}

// round 12
// speedup vs baseline: 1.2448x; 1.2448x over previous
#include <cuda_runtime.h>
#include <cstdint>

// ModelVoxel: out[p] = f[i,j,k] with i,j,k = (int)clip((x[p]+1)/h, 0, 255),
// h = 2/255, f is 256^3 fp32 (64 MB, mostly L2-resident via evict_last hint).
//
// R11: revert to the proven R7 4-pt/thread body (26 regs, 86.8% occ, 86.5us;
// both 8-pt variants regressed), and make it PERSISTENT grid-stride:
// exactly one wave (152 SMs x 8 CTAs x 256 thr), removing ~13 wave
// transitions (~1.3us each) and last-wave tail imbalance.
//  - x   -> __ldcs (evict-first streaming)
//  - out -> __stcs
//  - f   -> ld.global.nc.L2::cache_hint + createpolicy evict_last

static __device__ __forceinline__ int vox1(float v) {
    const float h = 2.0f / 255.0f;           // replicate reference's fp32 h
    float p = (v + 1.0f) / h;                // same op order as reference
    p = fminf(fmaxf(p, 0.0f), 255.0f);       // clip
    return (int)p;                           // truncation == astype(int32) (p >= 0)
}

static __device__ __forceinline__ uint64_t make_evict_last_policy() {
    uint64_t pol;
    asm("createpolicy.fractional.L2::evict_last.b64 %0, 1.0;" : "=l"(pol));
    return pol;
}

static __device__ __forceinline__ float ldg_pin_l2(const float* p, uint64_t pol) {
    float v;
    asm("ld.global.nc.L2::cache_hint.f32 %0, [%1], %2;"
        : "=f"(v) : "l"(p), "l"(pol));
    return v;
}

__global__ void __launch_bounds__(256) voxel_gather_persist_kernel(
    const float4* __restrict__ x4,   // 3 float4s per 4 points
    const float*  __restrict__ f,    // 256^3 grid
    float4*       __restrict__ out4, // 1 float4 per 4 points
    int n4)                          // number of 4-point groups
{
    const uint64_t pol = make_evict_last_policy();
    const int stride = gridDim.x * blockDim.x;

    for (int t = blockIdx.x * blockDim.x + threadIdx.x; t < n4; t += stride) {
        const float4* p = x4 + 3 * (size_t)t;
        float4 a = __ldcs(p + 0);   // streaming: evict-first, keep L2 for f
        float4 b = __ldcs(p + 1);
        float4 c = __ldcs(p + 2);

        // point 0: (a.x, a.y, a.z)  point 1: (a.w, b.x, b.y)
        // point 2: (b.z, b.w, c.x)  point 3: (c.y, c.z, c.w)
        int i0 = (vox1(a.x) << 16) | (vox1(a.y) << 8) | vox1(a.z);
        int i1 = (vox1(a.w) << 16) | (vox1(b.x) << 8) | vox1(b.y);
        int i2 = (vox1(b.z) << 16) | (vox1(b.w) << 8) | vox1(c.x);
        int i3 = (vox1(c.y) << 16) | (vox1(c.z) << 8) | vox1(c.w);

        float4 o;
        o.x = ldg_pin_l2(f + i0, pol);   // evict_last: pin gather table in L2
        o.y = ldg_pin_l2(f + i1, pol);
        o.z = ldg_pin_l2(f + i2, pol);
        o.w = ldg_pin_l2(f + i3, pol);
        __stcs(out4 + t, o);             // streaming store
    }
}

// Tail handler for n not divisible by 4 (not needed for 16777216, but cheap).
__global__ void voxel_gather_tail_kernel(
    const float* __restrict__ x,
    const float* __restrict__ f,
    float*       __restrict__ out,
    int start, int n)
{
    int i = start + blockIdx.x * blockDim.x + threadIdx.x;
    if (i >= n) return;
    const uint64_t pol = make_evict_last_policy();
    int ix = vox1(x[3 * (size_t)i + 0]);
    int iy = vox1(x[3 * (size_t)i + 1]);
    int iz = vox1(x[3 * (size_t)i + 2]);
    out[i] = ldg_pin_l2(f + ((ix << 16) | (iy << 8) | iz), pol);
}

extern "C" void kernel_launch(void* const* d_in, const int* in_sizes, int n_in,
                              void* d_out, int out_size) {
    const float* x = (const float*)d_in[0];   // (N, 3) fp32
    const float* f = (const float*)d_in[1];   // (256,256,256) fp32
    float* out = (float*)d_out;               // (N,) fp32

    int n  = in_sizes[0] / 3;                 // number of points
    int n4 = n / 4;

    if (n4 > 0) {
        // Persistent single-wave grid: GB300 has 152 SMs; 8 CTAs/SM at
        // 256 thr (26 regs) fills the 64-warp/SM budget -> 1216 CTAs.
        int threads = 256;
        int blocks = 152 * 8;
        int max_blocks = (n4 + threads - 1) / threads;
        if (blocks > max_blocks) blocks = max_blocks;
        voxel_gather_persist_kernel<<<blocks, threads>>>(
            (const float4*)x, f, (float4*)out, n4);
    }
    int rem_start = n4 * 4;
    if (rem_start < n) {
        int rem = n - rem_start;
        voxel_gather_tail_kernel<<<(rem + 255) / 256, 256>>>(
            x, f, out, rem_start, n);
    }
}

// round 13
// speedup vs baseline: 1.3136x; 1.0553x over previous
#include <cuda_runtime.h>
#include <cstdint>

// ModelVoxel: out[p] = f[i,j,k] with i,j,k = (int)clip((x[p]+1)/h, 0, 255),
// h = 2/255, f is 256^3 fp32 (64 MB, mostly L2-resident via evict_last hint).
//
// R12: persistent grid (R11 win) + cross-iteration software pipeline:
//   iter n: idx -> issue 4 gathers -> issue iter n+1's 3 streaming loads
//           (fly while gathers are in flight) -> STG (waits on gathers).
// Per-warp outstanding memory ~doubles without lengthening the per-point
// dependent chain (the mistake of R9/R10). Grid size is derived from the
// occupancy API so the persistent grid always equals actual residency.
//  - x   -> __ldcs (evict-first streaming)
//  - out -> __stcs
//  - f   -> ld.global.nc.L2::cache_hint + createpolicy evict_last

static __device__ __forceinline__ int vox1(float v) {
    const float h = 2.0f / 255.0f;           // replicate reference's fp32 h
    float p = (v + 1.0f) / h;                // same op order as reference
    p = fminf(fmaxf(p, 0.0f), 255.0f);       // clip
    return (int)p;                           // truncation == astype(int32) (p >= 0)
}

static __device__ __forceinline__ uint64_t make_evict_last_policy() {
    uint64_t pol;
    asm("createpolicy.fractional.L2::evict_last.b64 %0, 1.0;" : "=l"(pol));
    return pol;
}

static __device__ __forceinline__ float ldg_pin_l2(const float* p, uint64_t pol) {
    float v;
    asm("ld.global.nc.L2::cache_hint.f32 %0, [%1], %2;"
        : "=f"(v) : "l"(p), "l"(pol));
    return v;
}

__global__ void __launch_bounds__(256) voxel_pipe_kernel(
    const float4* __restrict__ x4,   // 3 float4s per 4 points
    const float*  __restrict__ f,    // 256^3 grid
    float4*       __restrict__ out4, // 1 float4 per 4 points
    int n4)                          // number of 4-point groups
{
    const uint64_t pol = make_evict_last_policy();
    const int stride = gridDim.x * blockDim.x;
    int t = blockIdx.x * blockDim.x + threadIdx.x;
    if (t >= n4) return;

    // Prologue: load first group's coordinates.
    const float4* p = x4 + 3 * (size_t)t;
    float4 a = __ldcs(p + 0);
    float4 b = __ldcs(p + 1);
    float4 c = __ldcs(p + 2);

    while (true) {
        // Index math for current group.
        // point 0: (a.x,a.y,a.z) point 1: (a.w,b.x,b.y)
        // point 2: (b.z,b.w,c.x) point 3: (c.y,c.z,c.w)
        int i0 = (vox1(a.x) << 16) | (vox1(a.y) << 8) | vox1(a.z);
        int i1 = (vox1(a.w) << 16) | (vox1(b.x) << 8) | vox1(b.y);
        int i2 = (vox1(b.z) << 16) | (vox1(b.w) << 8) | vox1(c.x);
        int i3 = (vox1(c.y) << 16) | (vox1(c.z) << 8) | vox1(c.w);

        // Issue the 4 gathers (long latency)...
        float4 o;
        o.x = ldg_pin_l2(f + i0, pol);
        o.y = ldg_pin_l2(f + i1, pol);
        o.z = ldg_pin_l2(f + i2, pol);
        o.w = ldg_pin_l2(f + i3, pol);

        // ...then immediately issue next iteration's streaming loads so
        // they overlap the gather wait.
        int tn = t + stride;
        bool more = tn < n4;
        float4 an, bn, cn;
        if (more) {
            const float4* pn = x4 + 3 * (size_t)tn;
            an = __ldcs(pn + 0);
            bn = __ldcs(pn + 1);
            cn = __ldcs(pn + 2);
        }

        // Store waits on the gathers; the next loads are already in flight.
        __stcs(out4 + t, o);

        if (!more) break;
        a = an; b = bn; c = cn;
        t = tn;
    }
}

// Tail handler for n not divisible by 4 (not needed for 16777216, but cheap).
__global__ void voxel_gather_tail_kernel(
    const float* __restrict__ x,
    const float* __restrict__ f,
    float*       __restrict__ out,
    int start, int n)
{
    int i = start + blockIdx.x * blockDim.x + threadIdx.x;
    if (i >= n) return;
    const uint64_t pol = make_evict_last_policy();
    int ix = vox1(x[3 * (size_t)i + 0]);
    int iy = vox1(x[3 * (size_t)i + 1]);
    int iz = vox1(x[3 * (size_t)i + 2]);
    out[i] = ldg_pin_l2(f + ((ix << 16) | (iy << 8) | iz), pol);
}

extern "C" void kernel_launch(void* const* d_in, const int* in_sizes, int n_in,
                              void* d_out, int out_size) {
    const float* x = (const float*)d_in[0];   // (N, 3) fp32
    const float* f = (const float*)d_in[1];   // (256,256,256) fp32
    float* out = (float*)d_out;               // (N,) fp32

    int n  = in_sizes[0] / 3;                 // number of points
    int n4 = n / 4;

    if (n4 > 0) {
        int threads = 256;
        // Persistent grid sized to actual residency (reg-count dependent),
        // so no CTA waits behind another's full work share.
        int sms = 152;
        cudaDeviceGetAttribute(&sms, cudaDevAttrMultiProcessorCount, 0);
        int per_sm = 8;
        cudaOccupancyMaxActiveBlocksPerMultiprocessor(
            &per_sm, voxel_pipe_kernel, threads, 0);
        if (per_sm < 1) per_sm = 1;
        int blocks = sms * per_sm;
        int max_blocks = (n4 + threads - 1) / threads;
        if (blocks > max_blocks) blocks = max_blocks;
        voxel_pipe_kernel<<<blocks, threads>>>(
            (const float4*)x, f, (float4*)out, n4);
    }
    int rem_start = n4 * 4;
    if (rem_start < n) {
        int rem = n - rem_start;
        voxel_gather_tail_kernel<<<(rem + 255) / 256, 256>>>(
            x, f, out, rem_start, n);
    }
}

// round 14
// speedup vs baseline: 1.3173x; 1.0028x over previous
#include <cuda_runtime.h>
#include <cstdint>

// ModelVoxel: out[p] = f[i,j,k] with i,j,k = (int)clip((x[p]+1)/h, 0, 255),
// h = 2/255, f is 256^3 fp32 (64 MB, mostly L2-resident via evict_last hint).
//
// R13: depth-2 gather pipeline on top of R12's persistent prefetch loop.
// Schedule per iteration:
//   compute idx from x_{n+1} -> issue gathers o_{n+1}
//   -> issue x loads for n+2 -> store o_n (gathers one full iter old).
// Doubles per-warp outstanding gathers (4 -> 8) without lengthening the
// per-point dependent chain.
//  - x   -> __ldcs (evict-first streaming)
//  - out -> __stcs
//  - f   -> ld.global.nc.L2::cache_hint + createpolicy evict_last

static __device__ __forceinline__ int vox1(float v) {
    const float h = 2.0f / 255.0f;           // replicate reference's fp32 h
    float p = (v + 1.0f) / h;                // same op order as reference
    p = fminf(fmaxf(p, 0.0f), 255.0f);       // clip
    return (int)p;                           // truncation == astype(int32) (p >= 0)
}

static __device__ __forceinline__ uint64_t make_evict_last_policy() {
    uint64_t pol;
    asm("createpolicy.fractional.L2::evict_last.b64 %0, 1.0;" : "=l"(pol));
    return pol;
}

static __device__ __forceinline__ float ldg_pin_l2(const float* p, uint64_t pol) {
    float v;
    asm("ld.global.nc.L2::cache_hint.f32 %0, [%1], %2;"
        : "=f"(v) : "l"(p), "l"(pol));
    return v;
}

static __device__ __forceinline__ float4 gather4(
    const float* __restrict__ f, uint64_t pol,
    float4 a, float4 b, float4 c)
{
    // point 0: (a.x,a.y,a.z) point 1: (a.w,b.x,b.y)
    // point 2: (b.z,b.w,c.x) point 3: (c.y,c.z,c.w)
    int i0 = (vox1(a.x) << 16) | (vox1(a.y) << 8) | vox1(a.z);
    int i1 = (vox1(a.w) << 16) | (vox1(b.x) << 8) | vox1(b.y);
    int i2 = (vox1(b.z) << 16) | (vox1(b.w) << 8) | vox1(c.x);
    int i3 = (vox1(c.y) << 16) | (vox1(c.z) << 8) | vox1(c.w);
    float4 o;
    o.x = ldg_pin_l2(f + i0, pol);
    o.y = ldg_pin_l2(f + i1, pol);
    o.z = ldg_pin_l2(f + i2, pol);
    o.w = ldg_pin_l2(f + i3, pol);
    return o;
}

__global__ void __launch_bounds__(256) voxel_pipe2_kernel(
    const float4* __restrict__ x4,   // 3 float4s per 4 points
    const float*  __restrict__ f,    // 256^3 grid
    float4*       __restrict__ out4, // 1 float4 per 4 points
    int n4)                          // number of 4-point groups
{
    const uint64_t pol = make_evict_last_policy();
    const int stride = gridDim.x * blockDim.x;
    int t = blockIdx.x * blockDim.x + threadIdx.x;
    if (t >= n4) return;

    // ── Prologue: group t loaded, gathers issued; group t+stride loading ──
    const float4* p = x4 + 3 * (size_t)t;
    float4 a = __ldcs(p + 0);
    float4 b = __ldcs(p + 1);
    float4 c = __ldcs(p + 2);

    float4 o_prev = gather4(f, pol, a, b, c);   // gathers for t in flight

    int tn = t + stride;
    bool more = tn < n4;
    if (more) {
        const float4* pn = x4 + 3 * (size_t)tn;
        a = __ldcs(pn + 0);
        b = __ldcs(pn + 1);
        c = __ldcs(pn + 2);
    }

    // ── Steady state ──
    while (more) {
        // Issue gathers for tn (x arrived last iteration).
        float4 o_next = gather4(f, pol, a, b, c);

        // Issue x loads for tn+stride; they fly under o_next's gathers.
        int tnn = tn + stride;
        bool more2 = tnn < n4;
        if (more2) {
            const float4* pn = x4 + 3 * (size_t)tnn;
            a = __ldcs(pn + 0);
            b = __ldcs(pn + 1);
            c = __ldcs(pn + 2);
        }

        // Retire t: its gathers are a full iteration old -> no stall.
        __stcs(out4 + t, o_prev);

        o_prev = o_next;
        t = tn; tn = tnn; more = more2;
    }
    __stcs(out4 + t, o_prev);
}

// Tail handler for n not divisible by 4 (not needed for 16777216, but cheap).
__global__ void voxel_gather_tail_kernel(
    const float* __restrict__ x,
    const float* __restrict__ f,
    float*       __restrict__ out,
    int start, int n)
{
    int i = start + blockIdx.x * blockDim.x + threadIdx.x;
    if (i >= n) return;
    const uint64_t pol = make_evict_last_policy();
    int ix = vox1(x[3 * (size_t)i + 0]);
    int iy = vox1(x[3 * (size_t)i + 1]);
    int iz = vox1(x[3 * (size_t)i + 2]);
    out[i] = ldg_pin_l2(f + ((ix << 16) | (iy << 8) | iz), pol);
}

extern "C" void kernel_launch(void* const* d_in, const int* in_sizes, int n_in,
                              void* d_out, int out_size) {
    const float* x = (const float*)d_in[0];   // (N, 3) fp32
    const float* f = (const float*)d_in[1];   // (256,256,256) fp32
    float* out = (float*)d_out;               // (N,) fp32

    int n  = in_sizes[0] / 3;                 // number of points
    int n4 = n / 4;

    if (n4 > 0) {
        int threads = 256;
        // Persistent grid sized to actual residency (reg-count dependent).
        int sms = 152;
        cudaDeviceGetAttribute(&sms, cudaDevAttrMultiProcessorCount, 0);
        int per_sm = 8;
        cudaOccupancyMaxActiveBlocksPerMultiprocessor(
            &per_sm, voxel_pipe2_kernel, threads, 0);
        if (per_sm < 1) per_sm = 1;
        int blocks = sms * per_sm;
        int max_blocks = (n4 + threads - 1) / threads;
        if (blocks > max_blocks) blocks = max_blocks;
        voxel_pipe2_kernel<<<blocks, threads>>>(
            (const float4*)x, f, (float4*)out, n4);
    }
    int rem_start = n4 * 4;
    if (rem_start < n) {
        int rem = n - rem_start;
        voxel_gather_tail_kernel<<<(rem + 255) / 256, 256>>>(
            x, f, out, rem_start, n);
    }
}

// round 15
// speedup vs baseline: 1.3296x; 1.0093x over previous
#include <cuda_runtime.h>
#include <cstdint>

// ModelVoxel: out[p] = f[i,j,k] with i,j,k = (int)clip((x[p]+1)/h, 0, 255),
// h = 2/255, f is 256^3 fp32 (64 MB, mostly L2-resident via evict_last hint).
//
// R14: R13's depth-2 gather pipeline, launched as 128-thread blocks.
// R13 at 40 regs / 256-thr lost residency (6 CTAs/SM, 57.6% occ) and the
// doubled per-warp MLP only broke even. 128-thr blocks at the same 40 regs
// give 12 CTAs/SM = 48 warps = 75% occ -> R12 occupancy x R13 depth,
// with zero change to the compiled body (no reg-cap spill risk).
//  - x   -> __ldcs (evict-first streaming)
//  - out -> __stcs
//  - f   -> ld.global.nc.L2::cache_hint + createpolicy evict_last

#define VOX_THREADS 128

static __device__ __forceinline__ int vox1(float v) {
    const float h = 2.0f / 255.0f;           // replicate reference's fp32 h
    float p = (v + 1.0f) / h;                // same op order as reference
    p = fminf(fmaxf(p, 0.0f), 255.0f);       // clip
    return (int)p;                           // truncation == astype(int32) (p >= 0)
}

static __device__ __forceinline__ uint64_t make_evict_last_policy() {
    uint64_t pol;
    asm("createpolicy.fractional.L2::evict_last.b64 %0, 1.0;" : "=l"(pol));
    return pol;
}

static __device__ __forceinline__ float ldg_pin_l2(const float* p, uint64_t pol) {
    float v;
    asm("ld.global.nc.L2::cache_hint.f32 %0, [%1], %2;"
        : "=f"(v) : "l"(p), "l"(pol));
    return v;
}

static __device__ __forceinline__ float4 gather4(
    const float* __restrict__ f, uint64_t pol,
    float4 a, float4 b, float4 c)
{
    // point 0: (a.x,a.y,a.z) point 1: (a.w,b.x,b.y)
    // point 2: (b.z,b.w,c.x) point 3: (c.y,c.z,c.w)
    int i0 = (vox1(a.x) << 16) | (vox1(a.y) << 8) | vox1(a.z);
    int i1 = (vox1(a.w) << 16) | (vox1(b.x) << 8) | vox1(b.y);
    int i2 = (vox1(b.z) << 16) | (vox1(b.w) << 8) | vox1(c.x);
    int i3 = (vox1(c.y) << 16) | (vox1(c.z) << 8) | vox1(c.w);
    float4 o;
    o.x = ldg_pin_l2(f + i0, pol);
    o.y = ldg_pin_l2(f + i1, pol);
    o.z = ldg_pin_l2(f + i2, pol);
    o.w = ldg_pin_l2(f + i3, pol);
    return o;
}

__global__ void __launch_bounds__(VOX_THREADS) voxel_pipe2_kernel(
    const float4* __restrict__ x4,   // 3 float4s per 4 points
    const float*  __restrict__ f,    // 256^3 grid
    float4*       __restrict__ out4, // 1 float4 per 4 points
    int n4)                          // number of 4-point groups
{
    const uint64_t pol = make_evict_last_policy();
    const int stride = gridDim.x * blockDim.x;
    int t = blockIdx.x * blockDim.x + threadIdx.x;
    if (t >= n4) return;

    // ── Prologue: group t loaded, gathers issued; group t+stride loading ──
    const float4* p = x4 + 3 * (size_t)t;
    float4 a = __ldcs(p + 0);
    float4 b = __ldcs(p + 1);
    float4 c = __ldcs(p + 2);

    float4 o_prev = gather4(f, pol, a, b, c);   // gathers for t in flight

    int tn = t + stride;
    bool more = tn < n4;
    if (more) {
        const float4* pn = x4 + 3 * (size_t)tn;
        a = __ldcs(pn + 0);
        b = __ldcs(pn + 1);
        c = __ldcs(pn + 2);
    }

    // ── Steady state ──
    while (more) {
        // Issue gathers for tn (x arrived last iteration).
        float4 o_next = gather4(f, pol, a, b, c);

        // Issue x loads for tn+stride; they fly under o_next's gathers.
        int tnn = tn + stride;
        bool more2 = tnn < n4;
        if (more2) {
            const float4* pn = x4 + 3 * (size_t)tnn;
            a = __ldcs(pn + 0);
            b = __ldcs(pn + 1);
            c = __ldcs(pn + 2);
        }

        // Retire t: its gathers are a full iteration old -> no stall.
        __stcs(out4 + t, o_prev);

        o_prev = o_next;
        t = tn; tn = tnn; more = more2;
    }
    __stcs(out4 + t, o_prev);
}

// Tail handler for n not divisible by 4 (not needed for 16777216, but cheap).
__global__ void voxel_gather_tail_kernel(
    const float* __restrict__ x,
    const float* __restrict__ f,
    float*       __restrict__ out,
    int start, int n)
{
    int i = start + blockIdx.x * blockDim.x + threadIdx.x;
    if (i >= n) return;
    const uint64_t pol = make_evict_last_policy();
    int ix = vox1(x[3 * (size_t)i + 0]);
    int iy = vox1(x[3 * (size_t)i + 1]);
    int iz = vox1(x[3 * (size_t)i + 2]);
    out[i] = ldg_pin_l2(f + ((ix << 16) | (iy << 8) | iz), pol);
}

extern "C" void kernel_launch(void* const* d_in, const int* in_sizes, int n_in,
                              void* d_out, int out_size) {
    const float* x = (const float*)d_in[0];   // (N, 3) fp32
    const float* f = (const float*)d_in[1];   // (256,256,256) fp32
    float* out = (float*)d_out;               // (N,) fp32

    int n  = in_sizes[0] / 3;                 // number of points
    int n4 = n / 4;

    if (n4 > 0) {
        int threads = VOX_THREADS;
        // Persistent grid sized to actual residency (reg-count dependent).
        int sms = 152;
        cudaDeviceGetAttribute(&sms, cudaDevAttrMultiProcessorCount, 0);
        int per_sm = 12;
        cudaOccupancyMaxActiveBlocksPerMultiprocessor(
            &per_sm, voxel_pipe2_kernel, threads, 0);
        if (per_sm < 1) per_sm = 1;
        int blocks = sms * per_sm;
        int max_blocks = (n4 + threads - 1) / threads;
        if (blocks > max_blocks) blocks = max_blocks;
        voxel_pipe2_kernel<<<blocks, threads>>>(
            (const float4*)x, f, (float4*)out, n4);
    }
    int rem_start = n4 * 4;
    if (rem_start < n) {
        int rem = n - rem_start;
        voxel_gather_tail_kernel<<<(rem + 255) / 256, 256>>>(
            x, f, out, rem_start, n);
    }
}